// round 1
// baseline (speedup 1.0000x reference)
#include <cuda_runtime.h>

// Problem constants
#define NN 2048   // nodes
#define FF 64     // in features
#define HH 16     // hidden
#define OO 8      // out
#define TS 8192   // m-MLP lookup table size
#define D_LO 0.0f
#define D_HI 5.0f

// Scratch (no allocations allowed)
__device__ __align__(16) float  g_fsums[NN * OO];   // [N, O]
__device__ __align__(16) float2 g_table[TS];        // (value, slope) per cell

// ---------------------------------------------------------------------------
// Zero the accumulators (d_out is poisoned; f_sums/out are atomically built).
// ---------------------------------------------------------------------------
__global__ void init_kernel(float* __restrict__ out) {
    int i = blockIdx.x * blockDim.x + threadIdx.x;
    if (i < NN * OO) {
        out[i] = 0.0f;
        g_fsums[i] = 0.0f;
    }
}

// ---------------------------------------------------------------------------
// Per-feature f MLPs: f_sums[n,o] = sum_f ( MLP_f(x[n,f]) )[o]
// One block per (feature, 256-node chunk). Weights for the feature in SMEM.
// ---------------------------------------------------------------------------
__global__ void f_kernel(const float* __restrict__ x,
                         const float* __restrict__ fW1, const float* __restrict__ fb1,
                         const float* __restrict__ fW2, const float* __restrict__ fb2,
                         const float* __restrict__ fW3, const float* __restrict__ fb3) {
    __shared__ float sW1[HH], sb1[HH], sW2[HH * HH], sb2[HH], sW3[OO * HH], sb3[OO];
    const int f = blockIdx.x;
    const int tid = threadIdx.x;

    if (tid < HH) {
        sW1[tid] = fW1[f * HH + tid];
        sb1[tid] = fb1[f * HH + tid];
        sb2[tid] = fb2[f * HH + tid];
    }
    if (tid < OO) sb3[tid] = fb3[f * OO + tid];
    for (int i = tid; i < HH * HH; i += blockDim.x) sW2[i] = fW2[f * HH * HH + i];
    for (int i = tid; i < OO * HH; i += blockDim.x) sW3[i] = fW3[f * OO * HH + i];
    __syncthreads();

    const int n = blockIdx.y * blockDim.x + tid;
    const float xv = x[n * FF + f];

    float h1[HH];
#pragma unroll
    for (int h = 0; h < HH; h++)
        h1[h] = fmaxf(fmaf(xv, sW1[h], sb1[h]), 0.0f);

    float h2[HH];
#pragma unroll
    for (int g = 0; g < HH; g++) {
        float a = sb2[g];
#pragma unroll
        for (int h = 0; h < HH; h++) a = fmaf(sW2[g * HH + h], h1[h], a);
        h2[g] = fmaxf(a, 0.0f);
    }

#pragma unroll
    for (int o = 0; o < OO; o++) {
        float a = sb3[o];
#pragma unroll
        for (int h = 0; h < HH; h++) a = fmaf(sW3[o * HH + h], h2[h], a);
        atomicAdd(&g_fsums[n * OO + o], a);
    }
}

// ---------------------------------------------------------------------------
// m-MLP evaluated at a scalar d (used only to build the table).
// ---------------------------------------------------------------------------
__device__ __forceinline__ float m_eval(float d,
                                        const float* sW1, const float* sb1,
                                        const float* sW2, const float* sb2,
                                        const float* sW3, float b3) {
    float h1[HH];
#pragma unroll
    for (int h = 0; h < HH; h++)
        h1[h] = fmaxf(fmaf(d, sW1[h], sb1[h]), 0.0f);
    float h2[HH];
#pragma unroll
    for (int g = 0; g < HH; g++) {
        float a = sb2[g];
#pragma unroll
        for (int h = 0; h < HH; h++) a = fmaf(sW2[g * HH + h], h1[h], a);
        h2[g] = fmaxf(a, 0.0f);
    }
    float o = b3;
#pragma unroll
    for (int h = 0; h < HH; h++) o = fmaf(sW3[h], h2[h], o);
    return o;
}

// ---------------------------------------------------------------------------
// Build the piecewise-linear table: g_table[k] = (g(x_k), g(x_k+dx) - g(x_k)).
// g is piecewise-linear in d (scalar-input ReLU MLP), so the lerp is exact
// everywhere except the ~300 cells containing a kink (error ~1e-5 abs).
// ---------------------------------------------------------------------------
__global__ void table_kernel(const float* __restrict__ mW1, const float* __restrict__ mb1,
                             const float* __restrict__ mW2, const float* __restrict__ mb2,
                             const float* __restrict__ mW3, const float* __restrict__ mb3) {
    __shared__ float sW1[HH], sb1[HH], sW2[HH * HH], sb2[HH], sW3[HH];
    const int tid = threadIdx.x;
    if (tid < HH) {
        sW1[tid] = mW1[tid];
        sb1[tid] = mb1[tid];
        sb2[tid] = mb2[tid];
        sW3[tid] = mW3[tid];
    }
    for (int i = tid; i < HH * HH; i += blockDim.x) sW2[i] = mW2[i];
    __syncthreads();

    const float b3 = mb3[0];
    const int k = blockIdx.x * blockDim.x + tid;
    if (k >= TS) return;

    const float dx = (D_HI - D_LO) / (float)TS;
    const float x0 = D_LO + (float)k * dx;
    const float v0 = m_eval(x0, sW1, sb1, sW2, sb2, sW3, b3);
    const float v1 = m_eval(x0 + dx, sW1, sb1, sW2, sb2, sW3, b3);
    g_table[k] = make_float2(v0, v1 - v0);
}

// ---------------------------------------------------------------------------
// Main: pred[i,o] = sum_j (g(d[i,j]) / norm[i,j]) * f_sums[j,o]
// Block = 256 threads, handles 32 rows x 512 columns.
//   - table (64KB) + f_sums slice (16KB, split float4 lo/hi, conflict-free)
//     staged in SMEM
//   - warp handles 4 rows; lanes stride over j; warp-shuffle reduce;
//     atomicAdd partials (4 j-slices per output).
// ---------------------------------------------------------------------------
__global__ void main_kernel(const float* __restrict__ dmat,
                            const float* __restrict__ nmat,
                            float* __restrict__ out) {
    extern __shared__ float smem[];
    float2* stab  = (float2*)smem;                  // TS float2 = 64KB
    float4* fs_lo = (float4*)(smem + 2 * TS);       // 512 float4 (o=0..3)
    float4* fs_hi = fs_lo + 512;                    // 512 float4 (o=4..7)

    const int tid = threadIdx.x;

    // Stage table (4096 float4 = 8192 float2)
    {
        const float4* gt = (const float4*)g_table;
        float4* st4 = (float4*)stab;
        for (int i = tid; i < TS / 2; i += blockDim.x) st4[i] = gt[i];
    }
    // Stage f_sums slice for this block's j range
    const int jb = blockIdx.y * 512;
    {
        const float4* gf = (const float4*)(g_fsums + jb * OO);
        for (int i = tid; i < 512; i += blockDim.x) {
            fs_lo[i] = gf[2 * i];
            fs_hi[i] = gf[2 * i + 1];
        }
    }
    __syncthreads();

    const int warp = tid >> 5;
    const int lane = tid & 31;
    const int row0 = blockIdx.x * 32 + warp * 4;
    const float* dp = dmat + (size_t)row0 * NN + jb;
    const float* np = nmat + (size_t)row0 * NN + jb;

    float acc[4][OO];
#pragma unroll
    for (int r = 0; r < 4; r++)
#pragma unroll
        for (int o = 0; o < OO; o++) acc[r][o] = 0.0f;

    const float inv_dx = (float)TS / (D_HI - D_LO);

    for (int it = 0; it < 16; it++) {
        const int jl = it * 32 + lane;
        const float4 fa = fs_lo[jl];
        const float4 fb = fs_hi[jl];
#pragma unroll
        for (int r = 0; r < 4; r++) {
            const float dv = dp[r * NN + jl];
            const float nv = np[r * NN + jl];
            float t = (dv - D_LO) * inv_dx;
            int k = (int)t;
            k = max(0, min(k, TS - 1));
            const float fr = t - (float)k;
            const float2 tv = stab[k];
            const float m = fmaf(fr, tv.y, tv.x);
            const float w = __fdividef(m, nv);
            acc[r][0] = fmaf(w, fa.x, acc[r][0]);
            acc[r][1] = fmaf(w, fa.y, acc[r][1]);
            acc[r][2] = fmaf(w, fa.z, acc[r][2]);
            acc[r][3] = fmaf(w, fa.w, acc[r][3]);
            acc[r][4] = fmaf(w, fb.x, acc[r][4]);
            acc[r][5] = fmaf(w, fb.y, acc[r][5]);
            acc[r][6] = fmaf(w, fb.z, acc[r][6]);
            acc[r][7] = fmaf(w, fb.w, acc[r][7]);
        }
    }

    // Warp reduction + partial accumulation into out
#pragma unroll
    for (int r = 0; r < 4; r++) {
#pragma unroll
        for (int o = 0; o < OO; o++) {
            float v = acc[r][o];
            v += __shfl_xor_sync(0xffffffffu, v, 16);
            v += __shfl_xor_sync(0xffffffffu, v, 8);
            v += __shfl_xor_sync(0xffffffffu, v, 4);
            v += __shfl_xor_sync(0xffffffffu, v, 2);
            v += __shfl_xor_sync(0xffffffffu, v, 1);
            if (lane == 0) atomicAdd(&out[(row0 + r) * OO + o], v);
        }
    }
}

// ---------------------------------------------------------------------------
// Launch. Inputs (metadata order):
//  0 x, 1 node_distances, 2 normalization,
//  3 fW1, 4 fb1, 5 fW2, 6 fb2, 7 fW3, 8 fb3,
//  9 mW1, 10 mb1, 11 mW2, 12 mb2, 13 mW3, 14 mb3
// ---------------------------------------------------------------------------
extern "C" void kernel_launch(void* const* d_in, const int* in_sizes, int n_in,
                              void* d_out, int out_size) {
    const float* x   = (const float*)d_in[0];
    const float* nd  = (const float*)d_in[1];
    const float* nrm = (const float*)d_in[2];
    const float* fW1 = (const float*)d_in[3];
    const float* fb1 = (const float*)d_in[4];
    const float* fW2 = (const float*)d_in[5];
    const float* fb2 = (const float*)d_in[6];
    const float* fW3 = (const float*)d_in[7];
    const float* fb3 = (const float*)d_in[8];
    const float* mW1 = (const float*)d_in[9];
    const float* mb1 = (const float*)d_in[10];
    const float* mW2 = (const float*)d_in[11];
    const float* mb2 = (const float*)d_in[12];
    const float* mW3 = (const float*)d_in[13];
    const float* mb3 = (const float*)d_in[14];
    float* out = (float*)d_out;

    const int main_smem = 2 * TS * (int)sizeof(float) + 2 * 512 * (int)sizeof(float4); // 81920B
    cudaFuncSetAttribute(main_kernel, cudaFuncAttributeMaxDynamicSharedMemorySize, main_smem);

    init_kernel<<<(NN * OO + 255) / 256, 256>>>(out);
    f_kernel<<<dim3(FF, NN / 256), 256>>>(x, fW1, fb1, fW2, fb2, fW3, fb3);
    table_kernel<<<TS / 256, 256>>>(mW1, mb1, mW2, mb2, mW3, mb3);
    main_kernel<<<dim3(NN / 32, 4), 256, main_smem>>>(nd, nrm, out);
}

// round 9
// speedup vs baseline: 1.1712x; 1.1712x over previous
#include <cuda_runtime.h>

// Problem constants
#define NN 2048   // nodes
#define FF 64     // in features
#define HH 16     // hidden
#define OO 8      // out
#define TS 2048   // m-MLP lookup table size
#define D_HI 5.0f

// Scratch (no allocations allowed)
__device__ __align__(16) float  g_fpart[FF * NN * OO];  // per-feature partials, 4MB
__device__ __align__(16) float  g_fsums[NN * OO];       // [N, O]
__device__ __align__(16) float2 g_table[TS];            // (value, slope) per cell

// ---------------------------------------------------------------------------
// m-MLP evaluated at a scalar d (used only to build the table).
// ---------------------------------------------------------------------------
__device__ __forceinline__ float m_eval(float d,
                                        const float* sW1, const float* sb1,
                                        const float* sW2, const float* sb2,
                                        const float* sW3, float b3) {
    float h1[HH];
#pragma unroll
    for (int h = 0; h < HH; h++)
        h1[h] = fmaxf(fmaf(d, sW1[h], sb1[h]), 0.0f);
    float h2[HH];
#pragma unroll
    for (int g = 0; g < HH; g++) {
        float a = sb2[g];
#pragma unroll
        for (int h = 0; h < HH; h++) a = fmaf(sW2[g * HH + h], h1[h], a);
        h2[g] = fmaxf(a, 0.0f);
    }
    float o = b3;
#pragma unroll
    for (int h = 0; h < HH; h++) o = fmaf(sW3[h], h2[h], o);
    return o;
}

// ---------------------------------------------------------------------------
// Fused kernel: blocks (f, chunk) for f<FF compute the per-feature f-MLP and
// store partials (no atomics). Blocks with blockIdx.x==FF build the m table.
// ---------------------------------------------------------------------------
__global__ void ftab_kernel(const float* __restrict__ x,
                            const float* __restrict__ fW1, const float* __restrict__ fb1,
                            const float* __restrict__ fW2, const float* __restrict__ fb2,
                            const float* __restrict__ fW3, const float* __restrict__ fb3,
                            const float* __restrict__ mW1, const float* __restrict__ mb1,
                            const float* __restrict__ mW2, const float* __restrict__ mb2,
                            const float* __restrict__ mW3, const float* __restrict__ mb3) {
    const int tid = threadIdx.x;

    if (blockIdx.x == FF) {
        // ---- m-MLP table build: 8 blocks x 256 threads = 2048 entries ----
        __shared__ float mw1[HH], mbs1[HH], mw2[HH * HH], mbs2[HH], mw3[HH];
        if (tid < HH) {
            mw1[tid] = mW1[tid];
            mbs1[tid] = mb1[tid];
            mbs2[tid] = mb2[tid];
            mw3[tid] = mW3[tid];
        }
        for (int i = tid; i < HH * HH; i += blockDim.x) mw2[i] = mW2[i];
        __syncthreads();

        const float b3 = mb3[0];
        const int k = blockIdx.y * 256 + tid;
        const float dx = D_HI / (float)TS;
        const float x0 = (float)k * dx;
        const float v0 = m_eval(x0, mw1, mbs1, mw2, mbs2, mw3, b3);
        const float v1 = m_eval(x0 + dx, mw1, mbs1, mw2, mbs2, mw3, b3);
        g_table[k] = make_float2(v0, v1 - v0);
        return;
    }

    // ---- per-feature f MLP: block (f, 256-node chunk) ----
    __shared__ float sW1[HH], sb1[HH], sW2[HH * HH], sb2[HH], sW3[OO * HH], sb3[OO];
    const int f = blockIdx.x;
    if (tid < HH) {
        sW1[tid] = fW1[f * HH + tid];
        sb1[tid] = fb1[f * HH + tid];
        sb2[tid] = fb2[f * HH + tid];
    }
    if (tid < OO) sb3[tid] = fb3[f * OO + tid];
    for (int i = tid; i < HH * HH; i += blockDim.x) sW2[i] = fW2[f * HH * HH + i];
    for (int i = tid; i < OO * HH; i += blockDim.x) sW3[i] = fW3[f * OO * HH + i];
    __syncthreads();

    const int n = blockIdx.y * blockDim.x + tid;
    const float xv = x[n * FF + f];

    float h1[HH];
#pragma unroll
    for (int h = 0; h < HH; h++)
        h1[h] = fmaxf(fmaf(xv, sW1[h], sb1[h]), 0.0f);

    float h2[HH];
#pragma unroll
    for (int g = 0; g < HH; g++) {
        float a = sb2[g];
#pragma unroll
        for (int h = 0; h < HH; h++) a = fmaf(sW2[g * HH + h], h1[h], a);
        h2[g] = fmaxf(a, 0.0f);
    }

    float o0[OO];
#pragma unroll
    for (int o = 0; o < OO; o++) {
        float a = sb3[o];
#pragma unroll
        for (int h = 0; h < HH; h++) a = fmaf(sW3[o * HH + h], h2[h], a);
        o0[o] = a;
    }

    float4* dst = (float4*)(g_fpart + ((size_t)f * NN + n) * OO);
    dst[0] = make_float4(o0[0], o0[1], o0[2], o0[3]);
    dst[1] = make_float4(o0[4], o0[5], o0[6], o0[7]);
}

// ---------------------------------------------------------------------------
// Reduce partials over features + zero the (poisoned) output buffer.
// 64 blocks x 256 threads; thread i owns one (n,o) pair. Coalesced per f.
// ---------------------------------------------------------------------------
__global__ void reduce_init_kernel(float* __restrict__ out) {
    const int i = blockIdx.x * 256 + threadIdx.x;  // 0 .. N*O-1
    float s = 0.0f;
#pragma unroll 8
    for (int f = 0; f < FF; f++) s += g_fpart[f * (NN * OO) + i];
    g_fsums[i] = s;
    out[i] = 0.0f;
}

// ---------------------------------------------------------------------------
// Piecewise-linear m lookup + normalize -> weight.
// ---------------------------------------------------------------------------
__device__ __forceinline__ float wcalc(float d, float nv, const float2* stab,
                                       float inv_dx) {
    float t = d * inv_dx;
    int k = __float2int_rz(t);
    k = min(max(k, 0), TS - 1);
    const float fr = t - (float)k;
    const float2 tv = stab[k];
    return __fdividef(fmaf(fr, tv.y, tv.x), nv);
}

// ---------------------------------------------------------------------------
// Main: pred[i,o] = sum_j (g(d[i,j]) / norm[i,j]) * f_sums[j,o]
// Block = 256 thr (8 warps), 16 rows x 512 cols. Warp = 2 rows.
// smem: 16KB table + 16KB f_sums slice (split float4 lo/hi) = 32KB.
// float4 global loads for high MLP; shuffle-reduce; atomicAdd 4 partials.
// ---------------------------------------------------------------------------
__global__ void __launch_bounds__(256, 4)
main_kernel(const float* __restrict__ dmat,
            const float* __restrict__ nmat,
            float* __restrict__ out) {
    extern __shared__ float smem[];
    float2* stab  = (float2*)smem;                  // TS float2 = 16KB
    float4* fs_lo = (float4*)(smem + 2 * TS);       // 512 float4 (o=0..3)
    float4* fs_hi = fs_lo + 512;                    // 512 float4 (o=4..7)

    const int tid = threadIdx.x;

    {   // stage table: 1024 float4
        const float4* gt = (const float4*)g_table;
        float4* st4 = (float4*)stab;
#pragma unroll
        for (int i = tid; i < TS / 2; i += 256) st4[i] = gt[i];
    }
    const int jb = blockIdx.y * 512;
    {   // stage f_sums slice
        const float4* gf = (const float4*)(g_fsums + jb * OO);
#pragma unroll
        for (int i = tid; i < 512; i += 256) {
            fs_lo[i] = gf[2 * i];
            fs_hi[i] = gf[2 * i + 1];
        }
    }
    __syncthreads();

    const int warp = tid >> 5;
    const int lane = tid & 31;
    const int row0 = blockIdx.x * 16 + warp * 2;
    const float* dp0 = dmat + (size_t)row0 * NN + jb;
    const float* np0 = nmat + (size_t)row0 * NN + jb;

    float acc0[OO], acc1[OO];
#pragma unroll
    for (int o = 0; o < OO; o++) { acc0[o] = 0.0f; acc1[o] = 0.0f; }

    const float inv_dx = (float)TS / D_HI;

#pragma unroll
    for (int it = 0; it < 4; it++) {
        const int jl = it * 128 + lane * 4;
        const float4 da = *(const float4*)(dp0 + jl);
        const float4 db = *(const float4*)(dp0 + NN + jl);
        const float4 na = *(const float4*)(np0 + jl);
        const float4 nb = *(const float4*)(np0 + NN + jl);

        float w0[4], w1[4];
        w0[0] = wcalc(da.x, na.x, stab, inv_dx);
        w0[1] = wcalc(da.y, na.y, stab, inv_dx);
        w0[2] = wcalc(da.z, na.z, stab, inv_dx);
        w0[3] = wcalc(da.w, na.w, stab, inv_dx);
        w1[0] = wcalc(db.x, nb.x, stab, inv_dx);
        w1[1] = wcalc(db.y, nb.y, stab, inv_dx);
        w1[2] = wcalc(db.z, nb.z, stab, inv_dx);
        w1[3] = wcalc(db.w, nb.w, stab, inv_dx);

#pragma unroll
        for (int jj = 0; jj < 4; jj++) {
            const float4 fa = fs_lo[jl + jj];
            const float4 fb = fs_hi[jl + jj];
            acc0[0] = fmaf(w0[jj], fa.x, acc0[0]);
            acc0[1] = fmaf(w0[jj], fa.y, acc0[1]);
            acc0[2] = fmaf(w0[jj], fa.z, acc0[2]);
            acc0[3] = fmaf(w0[jj], fa.w, acc0[3]);
            acc0[4] = fmaf(w0[jj], fb.x, acc0[4]);
            acc0[5] = fmaf(w0[jj], fb.y, acc0[5]);
            acc0[6] = fmaf(w0[jj], fb.z, acc0[6]);
            acc0[7] = fmaf(w0[jj], fb.w, acc0[7]);
            acc1[0] = fmaf(w1[jj], fa.x, acc1[0]);
            acc1[1] = fmaf(w1[jj], fa.y, acc1[1]);
            acc1[2] = fmaf(w1[jj], fa.z, acc1[2]);
            acc1[3] = fmaf(w1[jj], fa.w, acc1[3]);
            acc1[4] = fmaf(w1[jj], fb.x, acc1[4]);
            acc1[5] = fmaf(w1[jj], fb.y, acc1[5]);
            acc1[6] = fmaf(w1[jj], fb.z, acc1[6]);
            acc1[7] = fmaf(w1[jj], fb.w, acc1[7]);
        }
    }

    // Warp reduction + partial accumulation into out
#pragma unroll
    for (int o = 0; o < OO; o++) {
        float v0 = acc0[o], v1 = acc1[o];
        v0 += __shfl_xor_sync(0xffffffffu, v0, 16);
        v1 += __shfl_xor_sync(0xffffffffu, v1, 16);
        v0 += __shfl_xor_sync(0xffffffffu, v0, 8);
        v1 += __shfl_xor_sync(0xffffffffu, v1, 8);
        v0 += __shfl_xor_sync(0xffffffffu, v0, 4);
        v1 += __shfl_xor_sync(0xffffffffu, v1, 4);
        v0 += __shfl_xor_sync(0xffffffffu, v0, 2);
        v1 += __shfl_xor_sync(0xffffffffu, v1, 2);
        v0 += __shfl_xor_sync(0xffffffffu, v0, 1);
        v1 += __shfl_xor_sync(0xffffffffu, v1, 1);
        if (lane == 0) {
            atomicAdd(&out[row0 * OO + o], v0);
            atomicAdd(&out[(row0 + 1) * OO + o], v1);
        }
    }
}

// ---------------------------------------------------------------------------
// Launch. Inputs (metadata order):
//  0 x, 1 node_distances, 2 normalization,
//  3 fW1, 4 fb1, 5 fW2, 6 fb2, 7 fW3, 8 fb3,
//  9 mW1, 10 mb1, 11 mW2, 12 mb2, 13 mW3, 14 mb3
// ---------------------------------------------------------------------------
extern "C" void kernel_launch(void* const* d_in, const int* in_sizes, int n_in,
                              void* d_out, int out_size) {
    const float* x   = (const float*)d_in[0];
    const float* nd  = (const float*)d_in[1];
    const float* nrm = (const float*)d_in[2];
    const float* fW1 = (const float*)d_in[3];
    const float* fb1 = (const float*)d_in[4];
    const float* fW2 = (const float*)d_in[5];
    const float* fb2 = (const float*)d_in[6];
    const float* fW3 = (const float*)d_in[7];
    const float* fb3 = (const float*)d_in[8];
    const float* mW1 = (const float*)d_in[9];
    const float* mb1 = (const float*)d_in[10];
    const float* mW2 = (const float*)d_in[11];
    const float* mb2 = (const float*)d_in[12];
    const float* mW3 = (const float*)d_in[13];
    const float* mb3 = (const float*)d_in[14];
    float* out = (float*)d_out;

    // f-MLP partials + m table (fused): (FF+1) x 8 blocks
    ftab_kernel<<<dim3(FF + 1, NN / 256), 256>>>(x, fW1, fb1, fW2, fb2, fW3, fb3,
                                                 mW1, mb1, mW2, mb2, mW3, mb3);
    // reduce partials over f, zero output
    reduce_init_kernel<<<(NN * OO) / 256, 256>>>(out);
    // main fused weight+matmul
    const int main_smem = 2 * TS * (int)sizeof(float) + 2 * 512 * (int)sizeof(float4); // 32KB
    main_kernel<<<dim3(NN / 16, 4), 256, main_smem>>>(nd, nrm, out);
}